// round 3
// baseline (speedup 1.0000x reference)
#include <cuda_runtime.h>
#include <cstdint>
#include <cstddef>

// ---------------------------------------------------------------------------
// Problem constants
// ---------------------------------------------------------------------------
#define DDIM 4096
#define BATCH 2048

// ---------------------------------------------------------------------------
// Device-global state (scratch; no allocations allowed in kernel_launch)
// ---------------------------------------------------------------------------
__device__ unsigned int g_hist[256];
__device__ unsigned int g_prefix;
__device__ unsigned int g_krem;
__device__ float        g_thr;

__device__ float g_W1[(size_t)DDIM * DDIM];
__device__ float g_W2[(size_t)DDIM * DDIM];
__device__ float g_W3[(size_t)DDIM * DDIM];
__device__ float g_B1[DDIM];
__device__ float g_B2[DDIM];
__device__ float g_B3[DDIM];
__device__ float g_h1[(size_t)BATCH * DDIM];
__device__ float g_h2[(size_t)BATCH * DDIM];

// ---------------------------------------------------------------------------
// Radix select: find exact j-th smallest (0-indexed) of all score values.
// Order-preserving key transform for fp32 (no NaNs in inputs):
//   key = (u & 0x80000000) ? ~u : (u | 0x80000000)    (ascending float order)
// ---------------------------------------------------------------------------
__global__ void rs_init(unsigned int k)
{
    int t = threadIdx.x;
    if (t < 256) g_hist[t] = 0u;
    if (t == 0) { g_prefix = 0u; g_krem = k; }
}

__global__ void rs_hist(const float* __restrict__ p, int n4, int shift)
{
    __shared__ unsigned int sh[256];
    for (int i = threadIdx.x; i < 256; i += blockDim.x) sh[i] = 0u;
    __syncthreads();

    const unsigned int pref = g_prefix;
    const float4* __restrict__ p4 = (const float4*)p;

    int i = blockIdx.x * blockDim.x + threadIdx.x;
    const int stride = gridDim.x * blockDim.x;
    for (; i < n4; i += stride) {
        float4 v = p4[i];
        float arr[4] = {v.x, v.y, v.z, v.w};
        #pragma unroll
        for (int c = 0; c < 4; c++) {
            unsigned int u   = __float_as_uint(arr[c]);
            unsigned int key = (u & 0x80000000u) ? ~u : (u | 0x80000000u);
            bool match = (shift == 24) || (((key ^ pref) >> (shift + 8)) == 0u);
            unsigned int bin = (key >> shift) & 0xffu;
            // warp-aggregate to survive heavy bin concentration (pass 1:
            // half of all uniform scores share one exponent -> one bin)
            unsigned int tag   = match ? bin : (256u + (threadIdx.x & 31u));
            unsigned int amask = __activemask();
            unsigned int peers = __match_any_sync(amask, tag);
            if (match) {
                int lead = __ffs(peers) - 1;
                if ((int)(threadIdx.x & 31u) == lead)
                    atomicAdd(&sh[bin], (unsigned int)__popc(peers));
            }
        }
    }
    __syncthreads();
    for (int i2 = threadIdx.x; i2 < 256; i2 += blockDim.x) {
        unsigned int cv = sh[i2];
        if (cv) atomicAdd(&g_hist[i2], cv);
    }
}

__global__ void rs_scan(int shift)
{
    __shared__ unsigned int s[256];
    const int t = threadIdx.x;
    unsigned int c = g_hist[t];
    g_hist[t] = 0u;                 // reset for next pass
    s[t] = c;
    __syncthreads();
    // Hillis-Steele inclusive scan over 256 bins
    #pragma unroll
    for (int off = 1; off < 256; off <<= 1) {
        unsigned int add = (t >= off) ? s[t - off] : 0u;
        __syncthreads();
        s[t] += add;
        __syncthreads();
    }
    const unsigned int inc = s[t];
    const unsigned int exc = inc - c;
    const unsigned int k   = g_krem;
    if (k >= exc && k < inc) {      // exactly one thread (bins with c==0 skip)
        unsigned int newpref = g_prefix | ((unsigned int)t << shift);
        g_prefix = newpref;
        g_krem   = k - exc;
        if (shift == 0) {
            unsigned int u = (newpref & 0x80000000u) ? (newpref ^ 0x80000000u)
                                                     : ~newpref;
            g_thr = __uint_as_float(u);
        }
    }
}

// ---------------------------------------------------------------------------
// Mask: out = w * (s >= thr)
// ---------------------------------------------------------------------------
__global__ void mask_mul(const float* __restrict__ w,
                         const float* __restrict__ s,
                         float* __restrict__ out, int n4)
{
    const float thr = g_thr;
    const float4* __restrict__ w4 = (const float4*)w;
    const float4* __restrict__ s4 = (const float4*)s;
    float4* __restrict__ o4 = (float4*)out;

    int i = blockIdx.x * blockDim.x + threadIdx.x;
    const int stride = gridDim.x * blockDim.x;
    for (; i < n4; i += stride) {
        float4 wv = w4[i];
        float4 sv = s4[i];
        float4 r;
        r.x = (sv.x >= thr) ? wv.x : 0.0f;
        r.y = (sv.y >= thr) ? wv.y : 0.0f;
        r.z = (sv.z >= thr) ? wv.z : 0.0f;
        r.w = (sv.w >= thr) ? wv.w : 0.0f;
        o4[i] = r;
    }
}

// ---------------------------------------------------------------------------
// SGEMM:  C[m,n] = sum_k A[m,k] * W[n,k] + bias[n]   (optional ReLU)
// A: [M,K] row-major, W: [N,K] row-major (both K-contiguous -> NT gemm)
// 128x128 tile, BK=8, 256 threads, 8x8 microtile, double-buffered SMEM.
// ---------------------------------------------------------------------------
template<int RELU>
__global__ void __launch_bounds__(256, 2) sgemm_bias_relu(
    const float* __restrict__ A,
    const float* __restrict__ W,
    const float* __restrict__ bias,
    float* __restrict__ C,
    int M, int N, int K)
{
    constexpr int BM = 128, BN = 128, BK = 8;
    __shared__ float As[2][BK][BM];
    __shared__ float Bs[2][BK][BN];

    const int tid = threadIdx.x;
    const int bx = blockIdx.x;   // N tile
    const int by = blockIdx.y;   // M tile

    // global load mapping: one float4 of A and one of W per thread per tile
    const int lrow = tid >> 1;          // 0..127
    const int lcol = (tid & 1) << 2;    // 0 or 4

    const float* Ap = A + (size_t)(by * BM + lrow) * K + lcol;
    const float* Wp = W + (size_t)(bx * BN + lrow) * K + lcol;

    const int tx = tid & 15;   // column group (8 cols)
    const int ty = tid >> 4;   // row group    (8 rows)

    float acc[8][8];
    #pragma unroll
    for (int i = 0; i < 8; i++)
        #pragma unroll
        for (int j = 0; j < 8; j++) acc[i][j] = 0.0f;

    // prologue: tile 0 -> buffer 0
    float4 a4 = *(const float4*)Ap;
    float4 b4 = *(const float4*)Wp;
    As[0][lcol + 0][lrow] = a4.x; As[0][lcol + 1][lrow] = a4.y;
    As[0][lcol + 2][lrow] = a4.z; As[0][lcol + 3][lrow] = a4.w;
    Bs[0][lcol + 0][lrow] = b4.x; Bs[0][lcol + 1][lrow] = b4.y;
    Bs[0][lcol + 2][lrow] = b4.z; Bs[0][lcol + 3][lrow] = b4.w;
    __syncthreads();

    const int nt = K / BK;
    for (int t = 0; t < nt; t++) {
        const int cur = t & 1;
        if (t + 1 < nt) {
            a4 = *(const float4*)(Ap + (size_t)(t + 1) * BK);
            b4 = *(const float4*)(Wp + (size_t)(t + 1) * BK);
        }
        #pragma unroll
        for (int kk = 0; kk < BK; kk++) {
            float4 ra0 = *(const float4*)(&As[cur][kk][ty * 8]);
            float4 ra1 = *(const float4*)(&As[cur][kk][ty * 8 + 4]);
            float4 rb0 = *(const float4*)(&Bs[cur][kk][tx * 8]);
            float4 rb1 = *(const float4*)(&Bs[cur][kk][tx * 8 + 4]);
            float ra[8] = {ra0.x, ra0.y, ra0.z, ra0.w, ra1.x, ra1.y, ra1.z, ra1.w};
            float rb[8] = {rb0.x, rb0.y, rb0.z, rb0.w, rb1.x, rb1.y, rb1.z, rb1.w};
            #pragma unroll
            for (int i = 0; i < 8; i++)
                #pragma unroll
                for (int j = 0; j < 8; j++)
                    acc[i][j] = fmaf(ra[i], rb[j], acc[i][j]);
        }
        if (t + 1 < nt) {
            const int nxt = cur ^ 1;
            As[nxt][lcol + 0][lrow] = a4.x; As[nxt][lcol + 1][lrow] = a4.y;
            As[nxt][lcol + 2][lrow] = a4.z; As[nxt][lcol + 3][lrow] = a4.w;
            Bs[nxt][lcol + 0][lrow] = b4.x; Bs[nxt][lcol + 1][lrow] = b4.y;
            Bs[nxt][lcol + 2][lrow] = b4.z; Bs[nxt][lcol + 3][lrow] = b4.w;
            __syncthreads();
        }
    }

    // epilogue: bias (+ReLU), vectorized store
    float bv[8];
    #pragma unroll
    for (int j = 0; j < 8; j++) bv[j] = bias[bx * BN + tx * 8 + j];

    #pragma unroll
    for (int i = 0; i < 8; i++) {
        float* crow = C + (size_t)(by * BM + ty * 8 + i) * N + bx * BN + tx * 8;
        float4 v0, v1;
        v0.x = acc[i][0] + bv[0]; v0.y = acc[i][1] + bv[1];
        v0.z = acc[i][2] + bv[2]; v0.w = acc[i][3] + bv[3];
        v1.x = acc[i][4] + bv[4]; v1.y = acc[i][5] + bv[5];
        v1.z = acc[i][6] + bv[6]; v1.w = acc[i][7] + bv[7];
        if (RELU) {
            v0.x = fmaxf(v0.x, 0.0f); v0.y = fmaxf(v0.y, 0.0f);
            v0.z = fmaxf(v0.z, 0.0f); v0.w = fmaxf(v0.w, 0.0f);
            v1.x = fmaxf(v1.x, 0.0f); v1.y = fmaxf(v1.y, 0.0f);
            v1.z = fmaxf(v1.z, 0.0f); v1.w = fmaxf(v1.w, 0.0f);
        }
        *(float4*)crow       = v0;
        *(float4*)(crow + 4) = v1;
    }
}

// ---------------------------------------------------------------------------
// kernel_launch
// ---------------------------------------------------------------------------
extern "C" void kernel_launch(void* const* d_in, const int* in_sizes, int n_in,
                              void* d_out, int out_size)
{
    const float* x   = (const float*)d_in[0];
    const float* w1  = (const float*)d_in[1];
    const float* b1  = (const float*)d_in[2];
    const float* w2  = (const float*)d_in[3];
    const float* b2  = (const float*)d_in[4];
    const float* w3  = (const float*)d_in[5];
    const float* b3  = (const float*)d_in[6];
    const float* sw1 = (const float*)d_in[7];
    const float* sb1 = (const float*)d_in[8];
    const float* sw2 = (const float*)d_in[9];
    const float* sb2 = (const float*)d_in[10];
    const float* sw3 = (const float*)d_in[11];
    const float* sb3 = (const float*)d_in[12];
    float* out = (float*)d_out;

    const int M = in_sizes[0] / DDIM;   // 2048

    // j = int((1 - sparsity) * total_scores), sparsity = 0.5
    long long total = 0;
    for (int i = 7; i <= 12; i++) total += (long long)in_sizes[i];
    const unsigned int j = (unsigned int)(total / 2);

    const int nW4 = (DDIM * DDIM) / 4;
    const int nB4 = DDIM / 4;

    // --- 1) exact global threshold via 4-pass radix select ---
    rs_init<<<1, 256>>>(j);
    for (int shift = 24; shift >= 0; shift -= 8) {
        rs_hist<<<1024, 256>>>(sw1, nW4, shift);
        rs_hist<<<1024, 256>>>(sw2, nW4, shift);
        rs_hist<<<1024, 256>>>(sw3, nW4, shift);
        rs_hist<<<4,    256>>>(sb1, nB4, shift);
        rs_hist<<<4,    256>>>(sb2, nB4, shift);
        rs_hist<<<4,    256>>>(sb3, nB4, shift);
        rs_scan<<<1, 256>>>(shift);
    }

    // --- scratch symbol addresses (queries only; capture-safe) ---
    float *pW1, *pW2, *pW3, *pB1, *pB2, *pB3, *ph1, *ph2;
    cudaGetSymbolAddress((void**)&pW1, g_W1);
    cudaGetSymbolAddress((void**)&pW2, g_W2);
    cudaGetSymbolAddress((void**)&pW3, g_W3);
    cudaGetSymbolAddress((void**)&pB1, g_B1);
    cudaGetSymbolAddress((void**)&pB2, g_B2);
    cudaGetSymbolAddress((void**)&pB3, g_B3);
    cudaGetSymbolAddress((void**)&ph1, g_h1);
    cudaGetSymbolAddress((void**)&ph2, g_h2);

    // --- 2) materialize masked weights and biases ---
    mask_mul<<<1024, 256>>>(w1, sw1, pW1, nW4);
    mask_mul<<<1024, 256>>>(w2, sw2, pW2, nW4);
    mask_mul<<<1024, 256>>>(w3, sw3, pW3, nW4);
    mask_mul<<<4,    256>>>(b1, sb1, pB1, nB4);
    mask_mul<<<4,    256>>>(b2, sb2, pB2, nB4);
    mask_mul<<<4,    256>>>(b3, sb3, pB3, nB4);

    // --- 3) three dependent GEMMs ---
    dim3 grid(DDIM / 128, M / 128);   // (32, 16)
    sgemm_bias_relu<1><<<grid, 256>>>(x,   pW1, pB1, ph1, M, DDIM, DDIM);
    sgemm_bias_relu<1><<<grid, 256>>>(ph1, pW2, pB2, ph2, M, DDIM, DDIM);
    sgemm_bias_relu<0><<<grid, 256>>>(ph2, pW3, pB3, out, M, DDIM, DDIM);

    (void)n_in; (void)out_size;
}

// round 4
// speedup vs baseline: 1.0016x; 1.0016x over previous
#include <cuda_runtime.h>
#include <cstdint>
#include <cstddef>

// ---------------------------------------------------------------------------
// Problem constants
// ---------------------------------------------------------------------------
#define DDIM 4096
#define BATCH 2048

// ---------------------------------------------------------------------------
// Device-global state (scratch; no allocations allowed in kernel_launch)
// ---------------------------------------------------------------------------
__device__ unsigned int g_hist[256];
__device__ unsigned int g_prefix;
__device__ unsigned int g_krem;
__device__ float        g_thr;

__device__ float g_W1[(size_t)DDIM * DDIM];
__device__ float g_W2[(size_t)DDIM * DDIM];
__device__ float g_W3[(size_t)DDIM * DDIM];
__device__ float g_B1[DDIM];
__device__ float g_B2[DDIM];
__device__ float g_B3[DDIM];
__device__ float g_h1[(size_t)BATCH * DDIM];
__device__ float g_h2[(size_t)BATCH * DDIM];

// ---------------------------------------------------------------------------
// Radix select: find exact j-th smallest (0-indexed) of all score values.
// Order-preserving key transform for fp32 (no NaNs in inputs):
//   key = (u & 0x80000000) ? ~u : (u | 0x80000000)    (ascending float order)
// ---------------------------------------------------------------------------
__global__ void rs_init(unsigned int k)
{
    int t = threadIdx.x;
    if (t < 256) g_hist[t] = 0u;
    if (t == 0) { g_prefix = 0u; g_krem = k; }
}

__global__ void rs_hist(const float* __restrict__ p, int n4, int shift)
{
    __shared__ unsigned int sh[256];
    for (int i = threadIdx.x; i < 256; i += blockDim.x) sh[i] = 0u;
    __syncthreads();

    const unsigned int pref = g_prefix;
    const float4* __restrict__ p4 = (const float4*)p;

    int i = blockIdx.x * blockDim.x + threadIdx.x;
    const int stride = gridDim.x * blockDim.x;
    for (; i < n4; i += stride) {
        float4 v = p4[i];
        float arr[4] = {v.x, v.y, v.z, v.w};
        #pragma unroll
        for (int c = 0; c < 4; c++) {
            unsigned int u   = __float_as_uint(arr[c]);
            unsigned int key = (u & 0x80000000u) ? ~u : (u | 0x80000000u);
            bool match = (shift == 24) || (((key ^ pref) >> (shift + 8)) == 0u);
            unsigned int bin = (key >> shift) & 0xffu;
            // warp-aggregate to survive heavy bin concentration (pass 1:
            // half of all uniform scores share one exponent -> one bin)
            unsigned int tag   = match ? bin : (256u + (threadIdx.x & 31u));
            unsigned int amask = __activemask();
            unsigned int peers = __match_any_sync(amask, tag);
            if (match) {
                int lead = __ffs(peers) - 1;
                if ((int)(threadIdx.x & 31u) == lead)
                    atomicAdd(&sh[bin], (unsigned int)__popc(peers));
            }
        }
    }
    __syncthreads();
    for (int i2 = threadIdx.x; i2 < 256; i2 += blockDim.x) {
        unsigned int cv = sh[i2];
        if (cv) atomicAdd(&g_hist[i2], cv);
    }
}

__global__ void rs_scan(int shift)
{
    __shared__ unsigned int s[256];
    const int t = threadIdx.x;
    unsigned int c = g_hist[t];
    g_hist[t] = 0u;                 // reset for next pass
    s[t] = c;
    __syncthreads();
    // Hillis-Steele inclusive scan over 256 bins
    #pragma unroll
    for (int off = 1; off < 256; off <<= 1) {
        unsigned int add = (t >= off) ? s[t - off] : 0u;
        __syncthreads();
        s[t] += add;
        __syncthreads();
    }
    const unsigned int inc = s[t];
    const unsigned int exc = inc - c;
    const unsigned int k   = g_krem;
    if (k >= exc && k < inc) {      // exactly one thread (bins with c==0 skip)
        unsigned int newpref = g_prefix | ((unsigned int)t << shift);
        g_prefix = newpref;
        g_krem   = k - exc;
        if (shift == 0) {
            unsigned int u = (newpref & 0x80000000u) ? (newpref ^ 0x80000000u)
                                                     : ~newpref;
            g_thr = __uint_as_float(u);
        }
    }
}

// ---------------------------------------------------------------------------
// Mask: out = w * (s >= thr)
// ---------------------------------------------------------------------------
__global__ void mask_mul(const float* __restrict__ w,
                         const float* __restrict__ s,
                         float* __restrict__ out, int n4)
{
    const float thr = g_thr;
    const float4* __restrict__ w4 = (const float4*)w;
    const float4* __restrict__ s4 = (const float4*)s;
    float4* __restrict__ o4 = (float4*)out;

    int i = blockIdx.x * blockDim.x + threadIdx.x;
    const int stride = gridDim.x * blockDim.x;
    for (; i < n4; i += stride) {
        float4 wv = w4[i];
        float4 sv = s4[i];
        float4 r;
        r.x = (sv.x >= thr) ? wv.x : 0.0f;
        r.y = (sv.y >= thr) ? wv.y : 0.0f;
        r.z = (sv.z >= thr) ? wv.z : 0.0f;
        r.w = (sv.w >= thr) ? wv.w : 0.0f;
        o4[i] = r;
    }
}

// ---------------------------------------------------------------------------
// SGEMM:  C[m,n] = sum_k A[m,k] * W[n,k] + bias[n]   (optional ReLU)
// A: [M,K] row-major, W: [N,K] row-major (both K-contiguous -> NT gemm)
// 128x128 tile, BK=8, 256 threads, 8x8 microtile, double-buffered SMEM.
// ---------------------------------------------------------------------------
template<int RELU>
__global__ void __launch_bounds__(256, 2) sgemm_bias_relu(
    const float* __restrict__ A,
    const float* __restrict__ W,
    const float* __restrict__ bias,
    float* __restrict__ C,
    int M, int N, int K)
{
    constexpr int BM = 128, BN = 128, BK = 8;
    __shared__ float As[2][BK][BM];
    __shared__ float Bs[2][BK][BN];

    const int tid = threadIdx.x;
    const int bx = blockIdx.x;   // N tile
    const int by = blockIdx.y;   // M tile

    // global load mapping: one float4 of A and one of W per thread per tile
    const int lrow = tid >> 1;          // 0..127
    const int lcol = (tid & 1) << 2;    // 0 or 4

    const float* Ap = A + (size_t)(by * BM + lrow) * K + lcol;
    const float* Wp = W + (size_t)(bx * BN + lrow) * K + lcol;

    const int tx = tid & 15;   // column group (8 cols)
    const int ty = tid >> 4;   // row group    (8 rows)

    float acc[8][8];
    #pragma unroll
    for (int i = 0; i < 8; i++)
        #pragma unroll
        for (int j = 0; j < 8; j++) acc[i][j] = 0.0f;

    // prologue: tile 0 -> buffer 0
    float4 a4 = *(const float4*)Ap;
    float4 b4 = *(const float4*)Wp;
    As[0][lcol + 0][lrow] = a4.x; As[0][lcol + 1][lrow] = a4.y;
    As[0][lcol + 2][lrow] = a4.z; As[0][lcol + 3][lrow] = a4.w;
    Bs[0][lcol + 0][lrow] = b4.x; Bs[0][lcol + 1][lrow] = b4.y;
    Bs[0][lcol + 2][lrow] = b4.z; Bs[0][lcol + 3][lrow] = b4.w;
    __syncthreads();

    const int nt = K / BK;
    for (int t = 0; t < nt; t++) {
        const int cur = t & 1;
        if (t + 1 < nt) {
            a4 = *(const float4*)(Ap + (size_t)(t + 1) * BK);
            b4 = *(const float4*)(Wp + (size_t)(t + 1) * BK);
        }
        #pragma unroll
        for (int kk = 0; kk < BK; kk++) {
            float4 ra0 = *(const float4*)(&As[cur][kk][ty * 8]);
            float4 ra1 = *(const float4*)(&As[cur][kk][ty * 8 + 4]);
            float4 rb0 = *(const float4*)(&Bs[cur][kk][tx * 8]);
            float4 rb1 = *(const float4*)(&Bs[cur][kk][tx * 8 + 4]);
            float ra[8] = {ra0.x, ra0.y, ra0.z, ra0.w, ra1.x, ra1.y, ra1.z, ra1.w};
            float rb[8] = {rb0.x, rb0.y, rb0.z, rb0.w, rb1.x, rb1.y, rb1.z, rb1.w};
            #pragma unroll
            for (int i = 0; i < 8; i++)
                #pragma unroll
                for (int j = 0; j < 8; j++)
                    acc[i][j] = fmaf(ra[i], rb[j], acc[i][j]);
        }
        if (t + 1 < nt) {
            const int nxt = cur ^ 1;
            As[nxt][lcol + 0][lrow] = a4.x; As[nxt][lcol + 1][lrow] = a4.y;
            As[nxt][lcol + 2][lrow] = a4.z; As[nxt][lcol + 3][lrow] = a4.w;
            Bs[nxt][lcol + 0][lrow] = b4.x; Bs[nxt][lcol + 1][lrow] = b4.y;
            Bs[nxt][lcol + 2][lrow] = b4.z; Bs[nxt][lcol + 3][lrow] = b4.w;
            __syncthreads();
        }
    }

    // epilogue: bias (+ReLU), vectorized store
    float bv[8];
    #pragma unroll
    for (int j = 0; j < 8; j++) bv[j] = bias[bx * BN + tx * 8 + j];

    #pragma unroll
    for (int i = 0; i < 8; i++) {
        float* crow = C + (size_t)(by * BM + ty * 8 + i) * N + bx * BN + tx * 8;
        float4 v0, v1;
        v0.x = acc[i][0] + bv[0]; v0.y = acc[i][1] + bv[1];
        v0.z = acc[i][2] + bv[2]; v0.w = acc[i][3] + bv[3];
        v1.x = acc[i][4] + bv[4]; v1.y = acc[i][5] + bv[5];
        v1.z = acc[i][6] + bv[6]; v1.w = acc[i][7] + bv[7];
        if (RELU) {
            v0.x = fmaxf(v0.x, 0.0f); v0.y = fmaxf(v0.y, 0.0f);
            v0.z = fmaxf(v0.z, 0.0f); v0.w = fmaxf(v0.w, 0.0f);
            v1.x = fmaxf(v1.x, 0.0f); v1.y = fmaxf(v1.y, 0.0f);
            v1.z = fmaxf(v1.z, 0.0f); v1.w = fmaxf(v1.w, 0.0f);
        }
        *(float4*)crow       = v0;
        *(float4*)(crow + 4) = v1;
    }
}

// ---------------------------------------------------------------------------
// kernel_launch
// ---------------------------------------------------------------------------
extern "C" void kernel_launch(void* const* d_in, const int* in_sizes, int n_in,
                              void* d_out, int out_size)
{
    const float* x   = (const float*)d_in[0];
    const float* w1  = (const float*)d_in[1];
    const float* b1  = (const float*)d_in[2];
    const float* w2  = (const float*)d_in[3];
    const float* b2  = (const float*)d_in[4];
    const float* w3  = (const float*)d_in[5];
    const float* b3  = (const float*)d_in[6];
    const float* sw1 = (const float*)d_in[7];
    const float* sb1 = (const float*)d_in[8];
    const float* sw2 = (const float*)d_in[9];
    const float* sb2 = (const float*)d_in[10];
    const float* sw3 = (const float*)d_in[11];
    const float* sb3 = (const float*)d_in[12];
    float* out = (float*)d_out;

    const int M = in_sizes[0] / DDIM;   // 2048

    // j = int((1 - sparsity) * total_scores), sparsity = 0.5
    long long total = 0;
    for (int i = 7; i <= 12; i++) total += (long long)in_sizes[i];
    const unsigned int j = (unsigned int)(total / 2);

    const int nW4 = (DDIM * DDIM) / 4;
    const int nB4 = DDIM / 4;

    // --- 1) exact global threshold via 4-pass radix select ---
    rs_init<<<1, 256>>>(j);
    for (int shift = 24; shift >= 0; shift -= 8) {
        rs_hist<<<1024, 256>>>(sw1, nW4, shift);
        rs_hist<<<1024, 256>>>(sw2, nW4, shift);
        rs_hist<<<1024, 256>>>(sw3, nW4, shift);
        rs_hist<<<4,    256>>>(sb1, nB4, shift);
        rs_hist<<<4,    256>>>(sb2, nB4, shift);
        rs_hist<<<4,    256>>>(sb3, nB4, shift);
        rs_scan<<<1, 256>>>(shift);
    }

    // --- scratch symbol addresses (queries only; capture-safe) ---
    float *pW1, *pW2, *pW3, *pB1, *pB2, *pB3, *ph1, *ph2;
    cudaGetSymbolAddress((void**)&pW1, g_W1);
    cudaGetSymbolAddress((void**)&pW2, g_W2);
    cudaGetSymbolAddress((void**)&pW3, g_W3);
    cudaGetSymbolAddress((void**)&pB1, g_B1);
    cudaGetSymbolAddress((void**)&pB2, g_B2);
    cudaGetSymbolAddress((void**)&pB3, g_B3);
    cudaGetSymbolAddress((void**)&ph1, g_h1);
    cudaGetSymbolAddress((void**)&ph2, g_h2);

    // --- 2) materialize masked weights and biases ---
    mask_mul<<<1024, 256>>>(w1, sw1, pW1, nW4);
    mask_mul<<<1024, 256>>>(w2, sw2, pW2, nW4);
    mask_mul<<<1024, 256>>>(w3, sw3, pW3, nW4);
    mask_mul<<<4,    256>>>(b1, sb1, pB1, nB4);
    mask_mul<<<4,    256>>>(b2, sb2, pB2, nB4);
    mask_mul<<<4,    256>>>(b3, sb3, pB3, nB4);

    // --- 3) three dependent GEMMs ---
    dim3 grid(DDIM / 128, M / 128);   // (32, 16)
    sgemm_bias_relu<1><<<grid, 256>>>(x,   pW1, pB1, ph1, M, DDIM, DDIM);
    sgemm_bias_relu<1><<<grid, 256>>>(ph1, pW2, pB2, ph2, M, DDIM, DDIM);
    sgemm_bias_relu<0><<<grid, 256>>>(ph2, pW3, pB3, out, M, DDIM, DDIM);

    (void)n_in; (void)out_size;
}

// round 6
// speedup vs baseline: 1.8321x; 1.8292x over previous
#include <cuda_runtime.h>
#include <cuda_bf16.h>
#include <cstdint>
#include <cstddef>

#define DDIM 4096
#define BATCH 2048

// ---------------------------------------------------------------------------
// Device-global scratch
// ---------------------------------------------------------------------------
__device__ unsigned int g_hist[256];
__device__ unsigned int g_prefix;
__device__ unsigned int g_krem;
__device__ float        g_thr;

__device__ __align__(128) __nv_bfloat16 g_W1hi[(size_t)DDIM * DDIM];
__device__ __align__(128) __nv_bfloat16 g_W1lo[(size_t)DDIM * DDIM];
__device__ __align__(128) __nv_bfloat16 g_W2hi[(size_t)DDIM * DDIM];
__device__ __align__(128) __nv_bfloat16 g_W2lo[(size_t)DDIM * DDIM];
__device__ __align__(128) __nv_bfloat16 g_W3hi[(size_t)DDIM * DDIM];
__device__ __align__(128) __nv_bfloat16 g_W3lo[(size_t)DDIM * DDIM];
__device__ __align__(128) __nv_bfloat16 g_Xhi[(size_t)BATCH * DDIM];
__device__ __align__(128) __nv_bfloat16 g_Xlo[(size_t)BATCH * DDIM];
__device__ __align__(128) __nv_bfloat16 g_H1hi[(size_t)BATCH * DDIM];
__device__ __align__(128) __nv_bfloat16 g_H1lo[(size_t)BATCH * DDIM];
__device__ __align__(128) __nv_bfloat16 g_H2hi[(size_t)BATCH * DDIM];
__device__ __align__(128) __nv_bfloat16 g_H2lo[(size_t)BATCH * DDIM];
__device__ float g_B1[DDIM];
__device__ float g_B2[DDIM];
__device__ float g_B3[DDIM];

// ---------------------------------------------------------------------------
// Radix select (verified): exact j-th smallest of all score values.
// ---------------------------------------------------------------------------
__global__ void rs_init(unsigned int k)
{
    int t = threadIdx.x;
    if (t < 256) g_hist[t] = 0u;
    if (t == 0) { g_prefix = 0u; g_krem = k; }
}

__global__ void rs_hist(const float* __restrict__ p, int n4, int shift)
{
    __shared__ unsigned int sh[256];
    for (int i = threadIdx.x; i < 256; i += blockDim.x) sh[i] = 0u;
    __syncthreads();
    const unsigned int pref = g_prefix;
    const float4* __restrict__ p4 = (const float4*)p;
    int i = blockIdx.x * blockDim.x + threadIdx.x;
    const int stride = gridDim.x * blockDim.x;
    for (; i < n4; i += stride) {
        float4 v = p4[i];
        float arr[4] = {v.x, v.y, v.z, v.w};
        #pragma unroll
        for (int c = 0; c < 4; c++) {
            unsigned int u   = __float_as_uint(arr[c]);
            unsigned int key = (u & 0x80000000u) ? ~u : (u | 0x80000000u);
            bool match = (shift == 24) || (((key ^ pref) >> (shift + 8)) == 0u);
            unsigned int bin = (key >> shift) & 0xffu;
            unsigned int tag   = match ? bin : (256u + (threadIdx.x & 31u));
            unsigned int amask = __activemask();
            unsigned int peers = __match_any_sync(amask, tag);
            if (match) {
                int lead = __ffs(peers) - 1;
                if ((int)(threadIdx.x & 31u) == lead)
                    atomicAdd(&sh[bin], (unsigned int)__popc(peers));
            }
        }
    }
    __syncthreads();
    for (int i2 = threadIdx.x; i2 < 256; i2 += blockDim.x) {
        unsigned int cv = sh[i2];
        if (cv) atomicAdd(&g_hist[i2], cv);
    }
}

__global__ void rs_scan(int shift)
{
    __shared__ unsigned int s[256];
    const int t = threadIdx.x;
    unsigned int c = g_hist[t];
    g_hist[t] = 0u;
    s[t] = c;
    __syncthreads();
    #pragma unroll
    for (int off = 1; off < 256; off <<= 1) {
        unsigned int add = (t >= off) ? s[t - off] : 0u;
        __syncthreads();
        s[t] += add;
        __syncthreads();
    }
    const unsigned int inc = s[t];
    const unsigned int exc = inc - c;
    const unsigned int k   = g_krem;
    if (k >= exc && k < inc) {
        unsigned int newpref = g_prefix | ((unsigned int)t << shift);
        g_prefix = newpref;
        g_krem   = k - exc;
        if (shift == 0) {
            unsigned int u = (newpref & 0x80000000u) ? (newpref ^ 0x80000000u)
                                                     : ~newpref;
            g_thr = __uint_as_float(u);
        }
    }
}

// ---------------------------------------------------------------------------
// hi/lo split helpers + mask kernels
// ---------------------------------------------------------------------------
__device__ __forceinline__ void split2(float f0, float f1,
                                       unsigned int& h, unsigned int& l)
{
    __nv_bfloat16 h0 = __float2bfloat16(f0);
    __nv_bfloat16 h1 = __float2bfloat16(f1);
    __nv_bfloat16 l0 = __float2bfloat16(f0 - __bfloat162float(h0));
    __nv_bfloat16 l1 = __float2bfloat16(f1 - __bfloat162float(h1));
    h = (unsigned int)__bfloat16_as_ushort(h0) |
        ((unsigned int)__bfloat16_as_ushort(h1) << 16);
    l = (unsigned int)__bfloat16_as_ushort(l0) |
        ((unsigned int)__bfloat16_as_ushort(l1) << 16);
}

__global__ void mask_split(const float* __restrict__ w,
                           const float* __restrict__ s,
                           __nv_bfloat16* __restrict__ hi,
                           __nv_bfloat16* __restrict__ lo, int n4)
{
    const float thr = g_thr;
    const float4* __restrict__ w4 = (const float4*)w;
    const float4* __restrict__ s4 = (const float4*)s;
    uint2* __restrict__ h2 = (uint2*)hi;
    uint2* __restrict__ l2 = (uint2*)lo;
    int i = blockIdx.x * blockDim.x + threadIdx.x;
    const int stride = gridDim.x * blockDim.x;
    for (; i < n4; i += stride) {
        float4 wv = w4[i];
        float4 sv = s4[i];
        float f0 = (sv.x >= thr) ? wv.x : 0.0f;
        float f1 = (sv.y >= thr) ? wv.y : 0.0f;
        float f2 = (sv.z >= thr) ? wv.z : 0.0f;
        float f3 = (sv.w >= thr) ? wv.w : 0.0f;
        uint2 hu, lu;
        split2(f0, f1, hu.x, lu.x);
        split2(f2, f3, hu.y, lu.y);
        h2[i] = hu;
        l2[i] = lu;
    }
}

__global__ void split_plain(const float* __restrict__ in,
                            __nv_bfloat16* __restrict__ hi,
                            __nv_bfloat16* __restrict__ lo, int n4)
{
    const float4* __restrict__ p4 = (const float4*)in;
    uint2* __restrict__ h2 = (uint2*)hi;
    uint2* __restrict__ l2 = (uint2*)lo;
    int i = blockIdx.x * blockDim.x + threadIdx.x;
    const int stride = gridDim.x * blockDim.x;
    for (; i < n4; i += stride) {
        float4 v = p4[i];
        uint2 hu, lu;
        split2(v.x, v.y, hu.x, lu.x);
        split2(v.z, v.w, hu.y, lu.y);
        h2[i] = hu;
        l2[i] = lu;
    }
}

__global__ void mask_mul(const float* __restrict__ w,
                         const float* __restrict__ s,
                         float* __restrict__ out, int n4)
{
    const float thr = g_thr;
    const float4* __restrict__ w4 = (const float4*)w;
    const float4* __restrict__ s4 = (const float4*)s;
    float4* __restrict__ o4 = (float4*)out;
    int i = blockIdx.x * blockDim.x + threadIdx.x;
    const int stride = gridDim.x * blockDim.x;
    for (; i < n4; i += stride) {
        float4 wv = w4[i];
        float4 sv = s4[i];
        float4 r;
        r.x = (sv.x >= thr) ? wv.x : 0.0f;
        r.y = (sv.y >= thr) ? wv.y : 0.0f;
        r.z = (sv.z >= thr) ? wv.z : 0.0f;
        r.w = (sv.w >= thr) ? wv.w : 0.0f;
        o4[i] = r;
    }
}

// ---------------------------------------------------------------------------
// sm_100-baseline tensor-core primitives: cp.async + ldmatrix + mma.sync
// ---------------------------------------------------------------------------
__device__ __forceinline__ uint32_t smem_u32(const void* p)
{
    uint32_t a;
    asm("{ .reg .u64 t; cvta.to.shared.u64 t, %1; cvt.u32.u64 %0, t; }"
        : "=r"(a) : "l"(p));
    return a;
}

__device__ __forceinline__ void cpasync16(uint32_t dst, const void* src)
{
    asm volatile("cp.async.cg.shared.global [%0], [%1], 16;"
                 :: "r"(dst), "l"(src) : "memory");
}
#define CP_COMMIT() asm volatile("cp.async.commit_group;" ::: "memory")
#define CP_WAIT_1() asm volatile("cp.async.wait_group 1;" ::: "memory")

__device__ __forceinline__ void ldsm4(uint32_t& r0, uint32_t& r1,
                                      uint32_t& r2, uint32_t& r3, uint32_t a)
{
    asm volatile("ldmatrix.sync.aligned.m8n8.x4.shared.b16 {%0,%1,%2,%3}, [%4];"
                 : "=r"(r0), "=r"(r1), "=r"(r2), "=r"(r3) : "r"(a));
}

__device__ __forceinline__ void mma16816(float* c,
                                         uint32_t a0, uint32_t a1,
                                         uint32_t a2, uint32_t a3,
                                         uint32_t b0, uint32_t b1)
{
    asm volatile(
        "mma.sync.aligned.m16n8k16.row.col.f32.bf16.bf16.f32 "
        "{%0,%1,%2,%3}, {%4,%5,%6,%7}, {%8,%9}, {%0,%1,%2,%3};"
        : "+f"(c[0]), "+f"(c[1]), "+f"(c[2]), "+f"(c[3])
        : "r"(a0), "r"(a1), "r"(a2), "r"(a3), "r"(b0), "r"(b1));
}

// ---------------------------------------------------------------------------
// bf16x3 HMMA GEMM: C[128x128 tile] = A[M,K] @ B[N,K]^T + bias (opt ReLU)
// A,B given as bf16 hi/lo pairs (K-contiguous). 3-stage cp.async pipeline.
// 256 threads = 8 warps in 2(M) x 4(N); warp tile 64x32; BK=32.
// SMEM stage: Ah[128][32] Al Bh Bl bf16, 16B-chunk XOR swizzle (ch ^= row&3).
// ---------------------------------------------------------------------------
#define BM 128
#define BN 128
#define BK 32
#define GSTAGES 3
#define STG_B (4 * BM * BK * 2)        /* 32768 bytes per stage */
#define GSMEM  (GSTAGES * STG_B)       /* 98304 */

template<int RELU, int OUT_BF16>
__global__ void __launch_bounds__(256) gemm_hmma(
    const __nv_bfloat16* __restrict__ Ah, const __nv_bfloat16* __restrict__ Al,
    const __nv_bfloat16* __restrict__ Bh, const __nv_bfloat16* __restrict__ Bl,
    const float* __restrict__ bias,
    float* __restrict__ outf,
    __nv_bfloat16* __restrict__ outhi,
    __nv_bfloat16* __restrict__ outlo)
{
    extern __shared__ __align__(128) char smem[];
    const uint32_t sbase = smem_u32(smem);
    const int tid  = threadIdx.x;
    const int lane = tid & 31;
    const int wid  = tid >> 5;
    const int wm   = wid >> 2;          // 0..1
    const int wn   = wid & 3;           // 0..3
    const int bx   = blockIdx.x;        // N tile
    const int by   = blockIdx.y;        // M tile
    const int K    = DDIM;

    // --- global->shared load mapping: each thread owns 8 x 16B chunks ---
    const int lrow = tid >> 2;          // 0..63
    const int lch  = tid & 3;           // 16B chunk within 64B row
    const uint32_t d0 = (uint32_t)lrow * 64 + (uint32_t)((lch ^ (lrow & 3)) << 4);

    const int rowA = by * BM;
    const int rowB = bx * BN;
    const __nv_bfloat16* sAh0 = Ah + (size_t)(rowA + lrow) * K + lch * 8;
    const __nv_bfloat16* sAh1 = Ah + (size_t)(rowA + lrow + 64) * K + lch * 8;
    const __nv_bfloat16* sAl0 = Al + (size_t)(rowA + lrow) * K + lch * 8;
    const __nv_bfloat16* sAl1 = Al + (size_t)(rowA + lrow + 64) * K + lch * 8;
    const __nv_bfloat16* sBh0 = Bh + (size_t)(rowB + lrow) * K + lch * 8;
    const __nv_bfloat16* sBh1 = Bh + (size_t)(rowB + lrow + 64) * K + lch * 8;
    const __nv_bfloat16* sBl0 = Bl + (size_t)(rowB + lrow) * K + lch * 8;
    const __nv_bfloat16* sBl1 = Bl + (size_t)(rowB + lrow + 64) * K + lch * 8;

    #define LOAD_STAGE(stg, kt) do {                                          \
        const uint32_t s0 = sbase + (uint32_t)(stg) * STG_B + d0;             \
        const size_t ko = (size_t)(kt) * BK;                                  \
        cpasync16(s0,          sAh0 + ko);                                    \
        cpasync16(s0 + 4096,   sAh1 + ko);                                    \
        cpasync16(s0 + 8192,   sAl0 + ko);                                    \
        cpasync16(s0 + 12288,  sAl1 + ko);                                    \
        cpasync16(s0 + 16384,  sBh0 + ko);                                    \
        cpasync16(s0 + 20480,  sBh1 + ko);                                    \
        cpasync16(s0 + 24576,  sBl0 + ko);                                    \
        cpasync16(s0 + 28672,  sBl1 + ko);                                    \
    } while (0)

    float c[4][4][4];
    #pragma unroll
    for (int i = 0; i < 4; i++)
        #pragma unroll
        for (int j = 0; j < 4; j++)
            #pragma unroll
            for (int q = 0; q < 4; q++) c[i][j][q] = 0.0f;

    const int NT = K / BK;              // 128

    // prologue: stages 0..GSTAGES-2
    LOAD_STAGE(0, 0); CP_COMMIT();
    LOAD_STAGE(1, 1); CP_COMMIT();

    // ldmatrix per-lane addressing pieces
    const int fr = lane & 15;           // row within 16-row tile
    const int fh = lane >> 4;           // 0/1 -> +16B column chunk

    for (int t = 0; t < NT; t++) {
        CP_WAIT_1();
        __syncthreads();

        const int lt = t + GSTAGES - 1;
        if (lt < NT) LOAD_STAGE(lt % GSTAGES, lt);
        CP_COMMIT();

        const uint32_t sb = sbase + (uint32_t)(t % GSTAGES) * STG_B;
        // pass operands: (Ah,Bh), (Ah,Bl), (Al,Bh)
        const uint32_t paOff[3] = { 0u, 0u, 8192u };
        const uint32_t pbOff[3] = { 16384u, 24576u, 16384u };

        #pragma unroll
        for (int p = 0; p < 3; p++) {
            const uint32_t Ab = sb + paOff[p];
            const uint32_t Bb = sb + pbOff[p];
            #pragma unroll
            for (int kk = 0; kk < 2; kk++) {
                const int chb = kk * 2 + fh;   // 16B chunk index 0..3
                uint32_t a[4][4];
                #pragma unroll
                for (int mi = 0; mi < 4; mi++) {
                    const int row = wm * 64 + mi * 16 + fr;
                    const uint32_t ad = Ab + (uint32_t)row * 64 +
                                        (uint32_t)((chb ^ (row & 3)) << 4);
                    ldsm4(a[mi][0], a[mi][1], a[mi][2], a[mi][3], ad);
                }
                uint32_t b[2][4];
                #pragma unroll
                for (int nj = 0; nj < 2; nj++) {
                    const int row = wn * 32 + nj * 16 + fr;
                    const uint32_t bd = Bb + (uint32_t)row * 64 +
                                        (uint32_t)((chb ^ (row & 3)) << 4);
                    ldsm4(b[nj][0], b[nj][1], b[nj][2], b[nj][3], bd);
                }
                #pragma unroll
                for (int mi = 0; mi < 4; mi++) {
                    mma16816(c[mi][0], a[mi][0], a[mi][1], a[mi][2], a[mi][3],
                             b[0][0], b[0][2]);
                    mma16816(c[mi][1], a[mi][0], a[mi][1], a[mi][2], a[mi][3],
                             b[0][1], b[0][3]);
                    mma16816(c[mi][2], a[mi][0], a[mi][1], a[mi][2], a[mi][3],
                             b[1][0], b[1][2]);
                    mma16816(c[mi][3], a[mi][0], a[mi][1], a[mi][2], a[mi][3],
                             b[1][1], b[1][3]);
                }
            }
        }
    }

    // --- epilogue: bias (+ReLU), then fp32 store or bf16 hi/lo re-split ---
    const int q     = lane >> 2;        // 0..7
    const int rp    = lane & 3;         // column pair
    const int m0g   = by * BM + wm * 64;
    const int n0g   = bx * BN + wn * 32;

    #pragma unroll
    for (int mi = 0; mi < 4; mi++) {
        #pragma unroll
        for (int ni = 0; ni < 4; ni++) {
            const int col = n0g + ni * 8 + rp * 2;
            const float bv0 = __ldg(bias + col);
            const float bv1 = __ldg(bias + col + 1);
            float v0 = c[mi][ni][0] + bv0;
            float v1 = c[mi][ni][1] + bv1;
            float v2 = c[mi][ni][2] + bv0;
            float v3 = c[mi][ni][3] + bv1;
            if (RELU) {
                v0 = fmaxf(v0, 0.0f); v1 = fmaxf(v1, 0.0f);
                v2 = fmaxf(v2, 0.0f); v3 = fmaxf(v3, 0.0f);
            }
            const int r0 = m0g + mi * 16 + q;
            const int r1 = r0 + 8;
            if (OUT_BF16) {
                unsigned int h, l;
                split2(v0, v1, h, l);
                *(unsigned int*)(outhi + (size_t)r0 * DDIM + col) = h;
                *(unsigned int*)(outlo + (size_t)r0 * DDIM + col) = l;
                split2(v2, v3, h, l);
                *(unsigned int*)(outhi + (size_t)r1 * DDIM + col) = h;
                *(unsigned int*)(outlo + (size_t)r1 * DDIM + col) = l;
            } else {
                *(float2*)(outf + (size_t)r0 * DDIM + col) = make_float2(v0, v1);
                *(float2*)(outf + (size_t)r1 * DDIM + col) = make_float2(v2, v3);
            }
        }
    }
    #undef LOAD_STAGE
}

// ---------------------------------------------------------------------------
// kernel_launch
// ---------------------------------------------------------------------------
extern "C" void kernel_launch(void* const* d_in, const int* in_sizes, int n_in,
                              void* d_out, int out_size)
{
    const float* x   = (const float*)d_in[0];
    const float* w1  = (const float*)d_in[1];
    const float* b1  = (const float*)d_in[2];
    const float* w2  = (const float*)d_in[3];
    const float* b2  = (const float*)d_in[4];
    const float* w3  = (const float*)d_in[5];
    const float* b3  = (const float*)d_in[6];
    const float* sw1 = (const float*)d_in[7];
    const float* sb1 = (const float*)d_in[8];
    const float* sw2 = (const float*)d_in[9];
    const float* sb2 = (const float*)d_in[10];
    const float* sw3 = (const float*)d_in[11];
    const float* sb3 = (const float*)d_in[12];
    float* out = (float*)d_out;

    const int M = in_sizes[0] / DDIM;   // 2048

    long long total = 0;
    for (int i = 7; i <= 12; i++) total += (long long)in_sizes[i];
    const unsigned int j = (unsigned int)(total / 2);

    const int nW4 = (DDIM * DDIM) / 4;
    const int nB4 = DDIM / 4;
    const int nX4 = (M * DDIM) / 4;

    // --- 1) exact global threshold via 4-pass radix select ---
    rs_init<<<1, 256>>>(j);
    for (int shift = 24; shift >= 0; shift -= 8) {
        rs_hist<<<1024, 256>>>(sw1, nW4, shift);
        rs_hist<<<1024, 256>>>(sw2, nW4, shift);
        rs_hist<<<1024, 256>>>(sw3, nW4, shift);
        rs_hist<<<4,    256>>>(sb1, nB4, shift);
        rs_hist<<<4,    256>>>(sb2, nB4, shift);
        rs_hist<<<4,    256>>>(sb3, nB4, shift);
        rs_scan<<<1, 256>>>(shift);
    }

    // --- scratch symbol addresses ---
    __nv_bfloat16 *pW1h, *pW1l, *pW2h, *pW2l, *pW3h, *pW3l;
    __nv_bfloat16 *pXh, *pXl, *pH1h, *pH1l, *pH2h, *pH2l;
    float *pB1, *pB2, *pB3;
    cudaGetSymbolAddress((void**)&pW1h, g_W1hi);
    cudaGetSymbolAddress((void**)&pW1l, g_W1lo);
    cudaGetSymbolAddress((void**)&pW2h, g_W2hi);
    cudaGetSymbolAddress((void**)&pW2l, g_W2lo);
    cudaGetSymbolAddress((void**)&pW3h, g_W3hi);
    cudaGetSymbolAddress((void**)&pW3l, g_W3lo);
    cudaGetSymbolAddress((void**)&pXh,  g_Xhi);
    cudaGetSymbolAddress((void**)&pXl,  g_Xlo);
    cudaGetSymbolAddress((void**)&pH1h, g_H1hi);
    cudaGetSymbolAddress((void**)&pH1l, g_H1lo);
    cudaGetSymbolAddress((void**)&pH2h, g_H2hi);
    cudaGetSymbolAddress((void**)&pH2l, g_H2lo);
    cudaGetSymbolAddress((void**)&pB1,  g_B1);
    cudaGetSymbolAddress((void**)&pB2,  g_B2);
    cudaGetSymbolAddress((void**)&pB3,  g_B3);

    // --- 2) masked weights -> bf16 hi/lo ; masked biases fp32 ; split x ---
    mask_split<<<1024, 256>>>(w1, sw1, pW1h, pW1l, nW4);
    mask_split<<<1024, 256>>>(w2, sw2, pW2h, pW2l, nW4);
    mask_split<<<1024, 256>>>(w3, sw3, pW3h, pW3l, nW4);
    mask_mul<<<4, 256>>>(b1, sb1, pB1, nB4);
    mask_mul<<<4, 256>>>(b2, sb2, pB2, nB4);
    mask_mul<<<4, 256>>>(b3, sb3, pB3, nB4);
    split_plain<<<1024, 256>>>(x, pXh, pXl, nX4);

    // --- 3) three dependent bf16x3 HMMA GEMMs ---
    cudaFuncSetAttribute(gemm_hmma<1, 1>,
                         cudaFuncAttributeMaxDynamicSharedMemorySize, GSMEM);
    cudaFuncSetAttribute(gemm_hmma<0, 0>,
                         cudaFuncAttributeMaxDynamicSharedMemorySize, GSMEM);

    dim3 grid(DDIM / BN, M / BM);       // (32, 16)
    gemm_hmma<1, 1><<<grid, 256, GSMEM>>>(pXh,  pXl,  pW1h, pW1l, pB1,
                                          nullptr, pH1h, pH1l);
    gemm_hmma<1, 1><<<grid, 256, GSMEM>>>(pH1h, pH1l, pW2h, pW2l, pB2,
                                          nullptr, pH2h, pH2l);
    gemm_hmma<0, 0><<<grid, 256, GSMEM>>>(pH2h, pH2l, pW3h, pW3l, pB3,
                                          out, nullptr, nullptr);

    (void)n_in; (void)out_size;
}